// round 1
// baseline (speedup 1.0000x reference)
#include <cuda_runtime.h>
#include <cuda_bf16.h>

// Problem constants (ExportEquiDeformableAttn): bs=2, ns=50000, C=32, S=8, R=128
#define CC   32
#define RR   128
#define SPTS 8
#define MAXB 4

// Scratch: transposed planes [b][plane][y][x][c]  (channel-innermost => 128B coalesced corner reads)
__device__ float g_tp[(size_t)MAXB * 3 * RR * RR * CC];

// Preprocessed weights
__device__ float g_Wc[CC * 32];   // row c: [W_off row (24 cols) | W_w row (8 cols)]
__device__ float g_bc[32];        // [b_off (24) | b_w (8)]
__device__ float g_Wvo[CC * CC];  // W_v @ W_out
__device__ float g_bvo[CC];       // b_v @ W_out

// ---------------------------------------------------------------------------
// Prep 1: transpose planes (C,R,R) -> (R,R,C)
// One block per (b, plane, y) row: 128 x * 32 c = 4096 elems.
// ---------------------------------------------------------------------------
__global__ void transpose_planes(const float* __restrict__ xz,
                                 const float* __restrict__ xy,
                                 const float* __restrict__ yz) {
    int bid = blockIdx.x;                 // bs*3*R blocks
    int y   = bid % RR;
    int t   = bid / RR;
    int pl  = t % 3;
    int b   = t / 3;
    const float* src = (pl == 0) ? xz : (pl == 1) ? xy : yz;
    src += (size_t)b * CC * RR * RR + (size_t)y * RR;
    float* dst = g_tp + (((size_t)(b * 3 + pl) * RR * RR) + (size_t)y * RR) * CC;

    for (int i = threadIdx.x; i < RR * CC; i += blockDim.x) {
        int c = i & 31;
        int x = i >> 5;
        dst[i] = src[(size_t)c * RR * RR + x];   // dst[x*32+c] coalesced write
    }
}

// ---------------------------------------------------------------------------
// Prep 2: fold weights.  g_Wc = [W_off | W_w], g_Wvo = W_v @ W_out, g_bvo = b_v @ W_out
// One block, 1024 threads: tid -> (c = tid>>5, k = tid&31)
// ---------------------------------------------------------------------------
__global__ void prep_weights(const float* __restrict__ W_off, const float* __restrict__ b_off,
                             const float* __restrict__ W_w,   const float* __restrict__ b_w,
                             const float* __restrict__ W_v,   const float* __restrict__ b_v,
                             const float* __restrict__ W_out) {
    int tid = threadIdx.x;
    int c = tid >> 5, k = tid & 31;

    g_Wc[tid] = (k < 24) ? W_off[c * 24 + k] : W_w[c * 8 + (k - 24)];

    float a = 0.f;
#pragma unroll
    for (int j = 0; j < 32; j++) a = fmaf(W_v[c * 32 + j], W_out[j * 32 + k], a);
    g_Wvo[tid] = a;

    if (c == 0) g_bc[k] = (k < 24) ? b_off[k] : b_w[k - 24];
    if (c == 1) {
        float a2 = 0.f;
#pragma unroll
        for (int j = 0; j < 32; j++) a2 = fmaf(b_v[j], W_out[j * 32 + k], a2);
        g_bvo[k] = a2;
    }
}

// ---------------------------------------------------------------------------
// Bilinear tap on a (R,R,C) plane; each lane reads its own channel.
// grid_sample border-pad + align_corners=True semantics (matches reference).
// ---------------------------------------------------------------------------
__device__ __forceinline__ float bilin(const float* __restrict__ pl, float u, float v, int lane) {
    u = __saturatef(u) * 127.f;     // clip to [0,1] then scale by R-1
    v = __saturatef(v) * 127.f;
    float uf = floorf(u), vf = floorf(v);
    int x0 = (int)uf, y0 = (int)vf;
    int x1 = min(x0 + 1, 127), y1 = min(y0 + 1, 127);
    float fx = u - uf, fy = v - vf;

    const float* r0 = pl + ((size_t)y0 << 12);   // y0*128*32
    const float* r1 = pl + ((size_t)y1 << 12);
    int cx0 = (x0 << 5) + lane;
    int cx1 = (x1 << 5) + lane;

    float f00 = __ldg(r0 + cx0);
    float f01 = __ldg(r0 + cx1);
    float f10 = __ldg(r1 + cx0);
    float f11 = __ldg(r1 + cx1);

    float top = fmaf(fx, f01 - f00, f00);
    float bot = fmaf(fx, f11 - f10, f10);
    return fmaf(fy, bot - top, top);
}

// Sum of the three plane samples.  XZ: (u=px, v=pz)  XY: (u=px, v=py)  YZ: (u=py, v=pz)
__device__ __forceinline__ float sample3(const float* __restrict__ tp,
                                         float px, float py, float pz, int lane) {
    return bilin(tp,                px, pz, lane)
         + bilin(tp + RR * RR * CC, px, py, lane)
         + bilin(tp + 2 * RR * RR * CC, py, pz, lane);
}

// ---------------------------------------------------------------------------
// Main fused kernel: warp per point, lane per channel.
// ---------------------------------------------------------------------------
__global__ void __launch_bounds__(256)
dat_kernel(const float* __restrict__ qp, const float* __restrict__ b_out,
           float* __restrict__ out, int ns, int npts) {
    __shared__ float sWc[1024], sWvo[1024];
    __shared__ float sbc[32], sbvo[32], sbout[32];

    for (int i = threadIdx.x; i < 1024; i += 256) {
        sWc[i]  = g_Wc[i];
        sWvo[i] = g_Wvo[i];
    }
    if (threadIdx.x < 32) {
        sbc[threadIdx.x]   = g_bc[threadIdx.x];
        sbvo[threadIdx.x]  = g_bvo[threadIdx.x];
        sbout[threadIdx.x] = b_out[threadIdx.x];
    }
    __syncthreads();

    int w    = (blockIdx.x * 256 + threadIdx.x) >> 5;   // global warp id = point id
    int lane = threadIdx.x & 31;
    if (w >= npts) return;                              // warp-uniform

    int b = w / ns;
    float p0 = qp[w * 3 + 0];
    float p1 = qp[w * 3 + 1];
    float p2 = qp[w * 3 + 2];
    const float* tp = g_tp + (size_t)b * 3 * RR * RR * CC;

    // ---- primary triplane sample: lane holds feature[lane] ----
    float feat = sample3(tp, p0, p1, p2, lane);

    // ---- GEMV: [off(24) | w(8)] = feature @ [W_off | W_w] + [b_off | b_w] ----
    float ow = sbc[lane];
#pragma unroll
    for (int c = 0; c < 32; c++)
        ow = fmaf(__shfl_sync(0xffffffffu, feat, c), sWc[c * 32 + lane], ow);

    // ---- S aux samples, accumulate A = sum_s w_s * aux_s, sw = sum_s w_s ----
    float A = 0.f, sw = 0.f;
#pragma unroll
    for (int s = 0; s < SPTS; s++) {
        float ox = __shfl_sync(0xffffffffu, ow, 3 * s + 0);
        float oy = __shfl_sync(0xffffffffu, ow, 3 * s + 1);
        float oz = __shfl_sync(0xffffffffu, ow, 3 * s + 2);
        float ws = __shfl_sync(0xffffffffu, ow, 24 + s);
        float aux = sample3(tp, p0 + ox, p1 + oy, p2 + oz, lane);
        A  = fmaf(ws, aux, A);
        sw += ws;
    }

    // ---- final: out = A @ (W_v@W_out) + sw*(b_v@W_out) + b_out + feature ----
    float o = fmaf(sw, sbvo[lane], sbout[lane]) + feat;
#pragma unroll
    for (int c = 0; c < 32; c++)
        o = fmaf(__shfl_sync(0xffffffffu, A, c), sWvo[c * 32 + lane], o);

    out[(size_t)w * 32 + lane] = o;   // coalesced 128B per warp
}

// ---------------------------------------------------------------------------
// kernel_launch — inputs in reference order:
// 0 query_pos  1 c_xz  2 c_xy  3 c_yz  4 W_off  5 b_off  6 W_w  7 b_w
// 8 W_v  9 b_v  10 W_out  11 b_out
// ---------------------------------------------------------------------------
extern "C" void kernel_launch(void* const* d_in, const int* in_sizes, int n_in,
                              void* d_out, int out_size) {
    const float* qp    = (const float*)d_in[0];
    const float* c_xz  = (const float*)d_in[1];
    const float* c_xy  = (const float*)d_in[2];
    const float* c_yz  = (const float*)d_in[3];
    const float* W_off = (const float*)d_in[4];
    const float* b_off = (const float*)d_in[5];
    const float* W_w   = (const float*)d_in[6];
    const float* b_w   = (const float*)d_in[7];
    const float* W_v   = (const float*)d_in[8];
    const float* b_v   = (const float*)d_in[9];
    const float* W_out = (const float*)d_in[10];
    const float* b_out = (const float*)d_in[11];

    int bs   = in_sizes[1] / (CC * RR * RR);   // = 2
    int ns   = in_sizes[0] / (bs * 3);         // = 50000
    int npts = bs * ns;

    transpose_planes<<<bs * 3 * RR, 256>>>(c_xz, c_xy, c_yz);
    prep_weights<<<1, 1024>>>(W_off, b_off, W_w, b_w, W_v, b_v, W_out);

    int nblocks = (npts * 32 + 255) / 256;
    dat_kernel<<<nblocks, 256>>>(qp, b_out, (float*)d_out, ns, npts);
}

// round 6
// speedup vs baseline: 1.1902x; 1.1902x over previous
#include <cuda_runtime.h>
#include <cuda_fp16.h>
#include <cuda_bf16.h>

// Problem constants (ExportEquiDeformableAttn): bs=2, ns=50000, C=32, S=8, R=128
#define CC     32
#define RR     128
#define SPTS   8
#define MAXB   4
#define FULL   0xffffffffu
#define NCELL  4096                 // 16x16x16 Morton cells
#define NBINS  (MAXB * NCELL)
#define MAXPTS 524288

// Scratch: transposed fp32 planes [b][plane][y][x][c]  (channel-innermost, 128B/texel)
__device__ float g_tp[(size_t)MAXB * 3 * RR * RR * CC];

// Sorting scratch
__device__ int g_cnt[NBINS];
__device__ int g_off[NBINS];
__device__ int g_key[MAXPTS];
__device__ int g_ord[MAXPTS];

// Preprocessed weights
__device__ float g_Wc[CC * 32];   // row c: [W_off row (24) | W_w row (8)]
__device__ float g_bc[32];
__device__ float g_Wvo[CC * CC];  // W_v @ W_out
__device__ float g_bvo[CC];       // b_v @ W_out

// ---------------------------------------------------------------------------
// Prep 1: transpose planes (C,R,R) -> (R,R,C) via shared tile (coalesced both ways)
// ---------------------------------------------------------------------------
__global__ void transpose_planes(const float* __restrict__ xz,
                                 const float* __restrict__ xy,
                                 const float* __restrict__ yz) {
    __shared__ float sm[32][129];
    int bid = blockIdx.x;                 // bs*3*R blocks
    int y   = bid % RR;
    int t   = bid / RR;
    int pl  = t % 3;
    int b   = t / 3;
    const float* src = (pl == 0) ? xz : (pl == 1) ? xy : yz;
    src += (size_t)b * CC * RR * RR + (size_t)y * RR;
    float* dst = g_tp + (((size_t)(b * 3 + pl) * RR * RR) + (size_t)y * RR) * CC;

    for (int i = threadIdx.x; i < RR * CC; i += blockDim.x) {
        int c = i >> 7, x = i & 127;
        sm[c][x] = src[(size_t)c * RR * RR + x];   // coalesced read
    }
    __syncthreads();
    for (int j = threadIdx.x; j < RR * CC; j += blockDim.x) {
        int x = j >> 5, c = j & 31;
        dst[j] = sm[c][x];                          // coalesced write
    }
}

// ---------------------------------------------------------------------------
// Prep 2: fold weights
// ---------------------------------------------------------------------------
__global__ void prep_weights(const float* __restrict__ W_off, const float* __restrict__ b_off,
                             const float* __restrict__ W_w,   const float* __restrict__ b_w,
                             const float* __restrict__ W_v,   const float* __restrict__ b_v,
                             const float* __restrict__ W_out) {
    int tid = threadIdx.x;
    int c = tid >> 5, k = tid & 31;

    g_Wc[tid] = (k < 24) ? W_off[c * 24 + k] : W_w[c * 8 + (k - 24)];

    float a = 0.f;
#pragma unroll
    for (int j = 0; j < 32; j++) a = fmaf(W_v[c * 32 + j], W_out[j * 32 + k], a);
    g_Wvo[tid] = a;

    if (c == 0) g_bc[k] = (k < 24) ? b_off[k] : b_w[k - 24];
    if (c == 1) {
        float a2 = 0.f;
#pragma unroll
        for (int j = 0; j < 32; j++) a2 = fmaf(b_v[j], W_out[j * 32 + k], a2);
        g_bvo[k] = a2;
    }
}

// ---------------------------------------------------------------------------
// Spatial counting sort: Morton(16^3) cell key per point (batch in high bits)
// ---------------------------------------------------------------------------
__device__ __forceinline__ int spread3(int v) {   // 4 bits -> positions 0,3,6,9
    return (v & 1) | ((v & 2) << 2) | ((v & 4) << 4) | ((v & 8) << 6);
}

__global__ void zero_bins() {
    int i = blockIdx.x * blockDim.x + threadIdx.x;
    if (i < NBINS) g_cnt[i] = 0;
}

__global__ void hist_keys(const float* __restrict__ qp, int ns, int npts) {
    int i = blockIdx.x * blockDim.x + threadIdx.x;
    if (i >= npts) return;
    int b = i / ns;
    int bx = min(15, max(0, (int)(qp[i * 3 + 0] * 16.f)));
    int by = min(15, max(0, (int)(qp[i * 3 + 1] * 16.f)));
    int bz = min(15, max(0, (int)(qp[i * 3 + 2] * 16.f)));
    int key = (b << 12) | spread3(bx) | (spread3(by) << 1) | (spread3(bz) << 2);
    g_key[i] = key;
    atomicAdd(&g_cnt[key], 1);
}

__global__ void scan_bins() {      // 1024 threads, 16 bins each, exclusive scan
    __shared__ int s[1024];
    int t = threadIdx.x;
    int loc[16];
    int sum = 0;
#pragma unroll
    for (int i = 0; i < 16; i++) { loc[i] = sum; sum += g_cnt[t * 16 + i]; }
    s[t] = sum;
    __syncthreads();
    for (int off = 1; off < 1024; off <<= 1) {
        int v = (t >= off) ? s[t - off] : 0;
        __syncthreads();
        s[t] += v;
        __syncthreads();
    }
    int pre = (t > 0) ? s[t - 1] : 0;
#pragma unroll
    for (int i = 0; i < 16; i++) g_off[t * 16 + i] = pre + loc[i];
}

__global__ void scatter_order(int npts) {
    int i = blockIdx.x * blockDim.x + threadIdx.x;
    if (i >= npts) return;
    int pos = atomicAdd(&g_off[g_key[i]], 1);
    g_ord[pos] = i;
}

// ---------------------------------------------------------------------------
// Bilinear tap on (R,R,C) plane; lane l (0..7) owns channels 4l..4l+3 (float4).
// Border padding + align_corners=True.
// ---------------------------------------------------------------------------
__device__ __forceinline__ float4 bilin4(const float* __restrict__ pl,
                                         float u, float v, int l) {
    u = __saturatef(u) * 127.f;
    v = __saturatef(v) * 127.f;
    float uf = floorf(u), vf = floorf(v);
    int x0 = (int)uf, y0 = (int)vf;
    int x1 = min(x0 + 1, 127), y1 = min(y0 + 1, 127);
    float fx = u - uf, fy = v - vf;

    const float4* r0 = (const float4*)(pl + ((size_t)y0 << 12));   // y*128*32 floats
    const float4* r1 = (const float4*)(pl + ((size_t)y1 << 12));
    int i0 = (x0 << 3) + l;     // float4 index: x*8 + l
    int i1 = (x1 << 3) + l;

    float4 f00 = __ldg(r0 + i0);
    float4 f01 = __ldg(r0 + i1);
    float4 f10 = __ldg(r1 + i0);
    float4 f11 = __ldg(r1 + i1);

    float4 top, bot, res;
    top.x = fmaf(fx, f01.x - f00.x, f00.x);
    top.y = fmaf(fx, f01.y - f00.y, f00.y);
    top.z = fmaf(fx, f01.z - f00.z, f00.z);
    top.w = fmaf(fx, f01.w - f00.w, f00.w);
    bot.x = fmaf(fx, f11.x - f10.x, f10.x);
    bot.y = fmaf(fx, f11.y - f10.y, f10.y);
    bot.z = fmaf(fx, f11.z - f10.z, f10.z);
    bot.w = fmaf(fx, f11.w - f10.w, f10.w);
    res.x = fmaf(fy, bot.x - top.x, top.x);
    res.y = fmaf(fy, bot.y - top.y, top.y);
    res.z = fmaf(fy, bot.z - top.z, top.z);
    res.w = fmaf(fy, bot.w - top.w, top.w);
    return res;
}

// XZ: (px,pz)  XY: (px,py)  YZ: (py,pz)
__device__ __forceinline__ float4 sample3(const float* __restrict__ tp,
                                          float px, float py, float pz, int l) {
    float4 a = bilin4(tp,                    px, pz, l);
    float4 b = bilin4(tp + RR * RR * CC,     px, py, l);
    float4 c = bilin4(tp + 2 * RR * RR * CC, py, pz, l);
    float4 r;
    r.x = a.x + b.x + c.x;
    r.y = a.y + b.y + c.y;
    r.z = a.z + b.z + c.z;
    r.w = a.w + b.w + c.w;
    return r;
}

#define COMP(v, k) ((k) == 0 ? (v).x : (k) == 1 ? (v).y : (k) == 2 ? (v).z : (v).w)

// ---------------------------------------------------------------------------
// Main fused kernel: 4 points/warp (8-lane subgroups), lane owns 4 channels.
// Points consumed in spatially-sorted order via g_ord; output scattered by
// original index (coalesced 128B per point anyway).
// ---------------------------------------------------------------------------
__global__ void __launch_bounds__(512)
dat_kernel(const float* __restrict__ qp, const float* __restrict__ b_out,
           float* __restrict__ out, int ns, int npts) {
    __shared__ float sWc[1024], sWvo[1024];
    __shared__ float sbc[32], sbvo[32], sbout[32];

    for (int i = threadIdx.x; i < 1024; i += 512) {
        sWc[i]  = g_Wc[i];
        sWvo[i] = g_Wvo[i];
    }
    if (threadIdx.x < 32) {
        sbc[threadIdx.x]   = g_bc[threadIdx.x];
        sbvo[threadIdx.x]  = g_bvo[threadIdx.x];
        sbout[threadIdx.x] = b_out[threadIdx.x];
    }
    __syncthreads();

    int l    = threadIdx.x & 7;                     // sub-lane: channels 4l..4l+3
    int slot = (blockIdx.x * 512 + threadIdx.x) >> 3;
    bool valid = slot < npts;
    int pt = g_ord[valid ? slot : 0];

    int b = pt / ns;
    float p0 = qp[pt * 3 + 0];
    float p1 = qp[pt * 3 + 1];
    float p2 = qp[pt * 3 + 2];
    const float* tp = g_tp + (size_t)b * 3 * RR * RR * CC;

    // ---- primary triplane sample ----
    float4 feat = sample3(tp, p0, p1, p2, l);

    // ---- GEMV: [off(24)|w(8)] = feature @ [W_off|W_w] + bias (4 outputs/lane) ----
    float4 ow = *(const float4*)&sbc[4 * l];
#pragma unroll
    for (int c = 0; c < 32; c++) {
        float fc = __shfl_sync(FULL, COMP(feat, c & 3), c >> 2, 8);
        float4 wv = *(const float4*)&sWc[c * 32 + 4 * l];
        ow.x = fmaf(fc, wv.x, ow.x);
        ow.y = fmaf(fc, wv.y, ow.y);
        ow.z = fmaf(fc, wv.z, ow.z);
        ow.w = fmaf(fc, wv.w, ow.w);
    }

    // ---- S aux samples: A = sum_s w_s * aux_s, sw = sum_s w_s ----
    float4 A = make_float4(0.f, 0.f, 0.f, 0.f);
    float sw = 0.f;
#pragma unroll
    for (int s = 0; s < SPTS; s++) {
        float ox = __shfl_sync(FULL, COMP(ow, (3 * s    ) & 3), (3 * s    ) >> 2, 8);
        float oy = __shfl_sync(FULL, COMP(ow, (3 * s + 1) & 3), (3 * s + 1) >> 2, 8);
        float oz = __shfl_sync(FULL, COMP(ow, (3 * s + 2) & 3), (3 * s + 2) >> 2, 8);
        float ws = __shfl_sync(FULL, COMP(ow, (24 + s) & 3),    (24 + s) >> 2,    8);
        float4 aux = sample3(tp, p0 + ox, p1 + oy, p2 + oz, l);
        A.x = fmaf(ws, aux.x, A.x);
        A.y = fmaf(ws, aux.y, A.y);
        A.z = fmaf(ws, aux.z, A.z);
        A.w = fmaf(ws, aux.w, A.w);
        sw += ws;
    }

    // ---- final: out = A @ (W_v@W_out) + sw*(b_v@W_out) + b_out + feature ----
    float4 o;
    o.x = fmaf(sw, sbvo[4 * l    ], sbout[4 * l    ]) + feat.x;
    o.y = fmaf(sw, sbvo[4 * l + 1], sbout[4 * l + 1]) + feat.y;
    o.z = fmaf(sw, sbvo[4 * l + 2], sbout[4 * l + 2]) + feat.z;
    o.w = fmaf(sw, sbvo[4 * l + 3], sbout[4 * l + 3]) + feat.w;
#pragma unroll
    for (int c = 0; c < 32; c++) {
        float ac = __shfl_sync(FULL, COMP(A, c & 3), c >> 2, 8);
        float4 wv = *(const float4*)&sWvo[c * 32 + 4 * l];
        o.x = fmaf(ac, wv.x, o.x);
        o.y = fmaf(ac, wv.y, o.y);
        o.z = fmaf(ac, wv.z, o.z);
        o.w = fmaf(ac, wv.w, o.w);
    }

    if (valid) ((float4*)out)[(size_t)pt * 8 + l] = o;
}

// ---------------------------------------------------------------------------
// kernel_launch — inputs: 0 query_pos 1 c_xz 2 c_xy 3 c_yz 4 W_off 5 b_off
//                         6 W_w 7 b_w 8 W_v 9 b_v 10 W_out 11 b_out
// ---------------------------------------------------------------------------
extern "C" void kernel_launch(void* const* d_in, const int* in_sizes, int n_in,
                              void* d_out, int out_size) {
    const float* qp    = (const float*)d_in[0];
    const float* c_xz  = (const float*)d_in[1];
    const float* c_xy  = (const float*)d_in[2];
    const float* c_yz  = (const float*)d_in[3];
    const float* W_off = (const float*)d_in[4];
    const float* b_off = (const float*)d_in[5];
    const float* W_w   = (const float*)d_in[6];
    const float* b_w   = (const float*)d_in[7];
    const float* W_v   = (const float*)d_in[8];
    const float* b_v   = (const float*)d_in[9];
    const float* W_out = (const float*)d_in[10];
    const float* b_out = (const float*)d_in[11];

    int bs   = in_sizes[1] / (CC * RR * RR);   // = 2
    int ns   = in_sizes[0] / (bs * 3);         // = 50000
    int npts = bs * ns;

    // plane transpose + weight folding (independent of sort)
    transpose_planes<<<bs * 3 * RR, 256>>>(c_xz, c_xy, c_yz);
    prep_weights<<<1, 1024>>>(W_off, b_off, W_w, b_w, W_v, b_v, W_out);

    // spatial counting sort
    zero_bins<<<(NBINS + 255) / 256, 256>>>();
    hist_keys<<<(npts + 255) / 256, 256>>>(qp, ns, npts);
    scan_bins<<<1, 1024>>>();
    scatter_order<<<(npts + 255) / 256, 256>>>(npts);

    // main fused kernel: 64 points per 512-thread block
    int nblocks = (npts + 63) / 64;
    dat_kernel<<<nblocks, 512>>>(qp, b_out, (float*)d_out, ns, npts);
}

// round 7
// speedup vs baseline: 1.2056x; 1.0129x over previous
#include <cuda_runtime.h>
#include <cuda_fp16.h>
#include <cuda_bf16.h>

// Problem constants (ExportEquiDeformableAttn): bs=2, ns=50000, C=32, S=8, R=128
#define CC     32
#define RR     128
#define SPTS   8
#define MAXB   4
#define FULL   0xffffffffu
#define NCELL  4096                 // 16x16x16 Morton cells
#define NBINS  (MAXB * NCELL)
#define MAXPTS 524288

// Scratch: transposed fp32 planes [b][plane][y][x][c]  (channel-innermost, 128B/texel)
__device__ float g_tp[(size_t)MAXB * 3 * RR * RR * CC];

// Sorting scratch
__device__ int g_cnt[NBINS];
__device__ int g_off[NBINS];
__device__ int g_key[MAXPTS];
__device__ int g_ord[MAXPTS];

// Preprocessed weights
__device__ float g_Wc[CC * 32];   // row c: [W_off row (24) | W_w row (8)]
__device__ float g_bc[32];
__device__ float g_Wvo[CC * CC];  // W_v @ W_out
__device__ float g_bvo[CC];       // b_v @ W_out

// ---------------------------------------------------------------------------
// Prep 1: transpose planes (C,R,R) -> (R,R,C) via shared tile (coalesced both ways)
// ---------------------------------------------------------------------------
__global__ void transpose_planes(const float* __restrict__ xz,
                                 const float* __restrict__ xy,
                                 const float* __restrict__ yz) {
    __shared__ float sm[32][129];
    int bid = blockIdx.x;                 // bs*3*R blocks
    int y   = bid % RR;
    int t   = bid / RR;
    int pl  = t % 3;
    int b   = t / 3;
    const float* src = (pl == 0) ? xz : (pl == 1) ? xy : yz;
    src += (size_t)b * CC * RR * RR + (size_t)y * RR;
    float* dst = g_tp + (((size_t)(b * 3 + pl) * RR * RR) + (size_t)y * RR) * CC;

    for (int i = threadIdx.x; i < RR * CC; i += blockDim.x) {
        int c = i >> 7, x = i & 127;
        sm[c][x] = src[(size_t)c * RR * RR + x];   // coalesced read
    }
    __syncthreads();
    for (int j = threadIdx.x; j < RR * CC; j += blockDim.x) {
        int x = j >> 5, c = j & 31;
        dst[j] = sm[c][x];                          // coalesced write
    }
}

// ---------------------------------------------------------------------------
// Prep 2: fold weights
// ---------------------------------------------------------------------------
__global__ void prep_weights(const float* __restrict__ W_off, const float* __restrict__ b_off,
                             const float* __restrict__ W_w,   const float* __restrict__ b_w,
                             const float* __restrict__ W_v,   const float* __restrict__ b_v,
                             const float* __restrict__ W_out) {
    int tid = threadIdx.x;
    int c = tid >> 5, k = tid & 31;

    g_Wc[tid] = (k < 24) ? W_off[c * 24 + k] : W_w[c * 8 + (k - 24)];

    float a = 0.f;
#pragma unroll
    for (int j = 0; j < 32; j++) a = fmaf(W_v[c * 32 + j], W_out[j * 32 + k], a);
    g_Wvo[tid] = a;

    if (c == 0) g_bc[k] = (k < 24) ? b_off[k] : b_w[k - 24];
    if (c == 1) {
        float a2 = 0.f;
#pragma unroll
        for (int j = 0; j < 32; j++) a2 = fmaf(b_v[j], W_out[j * 32 + k], a2);
        g_bvo[k] = a2;
    }
}

// ---------------------------------------------------------------------------
// Spatial counting sort: Morton(16^3) cell key per point (batch in high bits)
// ---------------------------------------------------------------------------
__device__ __forceinline__ int spread3(int v) {   // 4 bits -> positions 0,3,6,9
    return (v & 1) | ((v & 2) << 2) | ((v & 4) << 4) | ((v & 8) << 6);
}

__global__ void zero_bins() {
    int i = blockIdx.x * blockDim.x + threadIdx.x;
    if (i < NBINS) g_cnt[i] = 0;
}

__global__ void hist_keys(const float* __restrict__ qp, int ns, int npts) {
    int i = blockIdx.x * blockDim.x + threadIdx.x;
    if (i >= npts) return;
    int b = i / ns;
    int bx = min(15, max(0, (int)(qp[i * 3 + 0] * 16.f)));
    int by = min(15, max(0, (int)(qp[i * 3 + 1] * 16.f)));
    int bz = min(15, max(0, (int)(qp[i * 3 + 2] * 16.f)));
    int key = (b << 12) | spread3(bx) | (spread3(by) << 1) | (spread3(bz) << 2);
    g_key[i] = key;
    atomicAdd(&g_cnt[key], 1);
}

__global__ void scan_bins() {      // 1024 threads, 16 bins each, exclusive scan
    __shared__ int s[1024];
    int t = threadIdx.x;
    int loc[16];
    int sum = 0;
#pragma unroll
    for (int i = 0; i < 16; i++) { loc[i] = sum; sum += g_cnt[t * 16 + i]; }
    s[t] = sum;
    __syncthreads();
    for (int off = 1; off < 1024; off <<= 1) {
        int v = (t >= off) ? s[t - off] : 0;
        __syncthreads();
        s[t] += v;
        __syncthreads();
    }
    int pre = (t > 0) ? s[t - 1] : 0;
#pragma unroll
    for (int i = 0; i < 16; i++) g_off[t * 16 + i] = pre + loc[i];
}

__global__ void scatter_order(int npts) {
    int i = blockIdx.x * blockDim.x + threadIdx.x;
    if (i >= npts) return;
    int pos = atomicAdd(&g_off[g_key[i]], 1);
    g_ord[pos] = i;
}

// ---------------------------------------------------------------------------
// Bilinear tap on (R,R,C) plane; lane l (0..7) owns channels 4l..4l+3 (float4).
// Border padding + align_corners=True.
// ---------------------------------------------------------------------------
__device__ __forceinline__ float4 bilin4(const float* __restrict__ pl,
                                         float u, float v, int l) {
    u = __saturatef(u) * 127.f;
    v = __saturatef(v) * 127.f;
    float uf = floorf(u), vf = floorf(v);
    int x0 = (int)uf, y0 = (int)vf;
    int x1 = min(x0 + 1, 127), y1 = min(y0 + 1, 127);
    float fx = u - uf, fy = v - vf;

    const float4* r0 = (const float4*)(pl + ((size_t)y0 << 12));   // y*128*32 floats
    const float4* r1 = (const float4*)(pl + ((size_t)y1 << 12));
    int i0 = (x0 << 3) + l;     // float4 index: x*8 + l
    int i1 = (x1 << 3) + l;

    float4 f00 = __ldg(r0 + i0);
    float4 f01 = __ldg(r0 + i1);
    float4 f10 = __ldg(r1 + i0);
    float4 f11 = __ldg(r1 + i1);

    float4 top, bot, res;
    top.x = fmaf(fx, f01.x - f00.x, f00.x);
    top.y = fmaf(fx, f01.y - f00.y, f00.y);
    top.z = fmaf(fx, f01.z - f00.z, f00.z);
    top.w = fmaf(fx, f01.w - f00.w, f00.w);
    bot.x = fmaf(fx, f11.x - f10.x, f10.x);
    bot.y = fmaf(fx, f11.y - f10.y, f10.y);
    bot.z = fmaf(fx, f11.z - f10.z, f10.z);
    bot.w = fmaf(fx, f11.w - f10.w, f10.w);
    res.x = fmaf(fy, bot.x - top.x, top.x);
    res.y = fmaf(fy, bot.y - top.y, top.y);
    res.z = fmaf(fy, bot.z - top.z, top.z);
    res.w = fmaf(fy, bot.w - top.w, top.w);
    return res;
}

// XZ: (px,pz)  XY: (px,py)  YZ: (py,pz)
__device__ __forceinline__ float4 sample3(const float* __restrict__ tp,
                                          float px, float py, float pz, int l) {
    float4 a = bilin4(tp,                    px, pz, l);
    float4 b = bilin4(tp + RR * RR * CC,     px, py, l);
    float4 c = bilin4(tp + 2 * RR * RR * CC, py, pz, l);
    float4 r;
    r.x = a.x + b.x + c.x;
    r.y = a.y + b.y + c.y;
    r.z = a.z + b.z + c.z;
    r.w = a.w + b.w + c.w;
    return r;
}

#define COMP(v, k) ((k) == 0 ? (v).x : (k) == 1 ? (v).y : (k) == 2 ? (v).z : (v).w)

// ---------------------------------------------------------------------------
// Main fused kernel: 4 points/warp (8-lane subgroups), lane owns 4 channels.
// Points consumed in spatially-sorted order via g_ord; output scattered by
// original index (coalesced 128B per point anyway).
// ---------------------------------------------------------------------------
__global__ void __launch_bounds__(512)
dat_kernel(const float* __restrict__ qp, const float* __restrict__ b_out,
           float* __restrict__ out, int ns, int npts) {
    __shared__ float sWc[1024], sWvo[1024];
    __shared__ float sbc[32], sbvo[32], sbout[32];

    for (int i = threadIdx.x; i < 1024; i += 512) {
        sWc[i]  = g_Wc[i];
        sWvo[i] = g_Wvo[i];
    }
    if (threadIdx.x < 32) {
        sbc[threadIdx.x]   = g_bc[threadIdx.x];
        sbvo[threadIdx.x]  = g_bvo[threadIdx.x];
        sbout[threadIdx.x] = b_out[threadIdx.x];
    }
    __syncthreads();

    int l    = threadIdx.x & 7;                     // sub-lane: channels 4l..4l+3
    int slot = (blockIdx.x * 512 + threadIdx.x) >> 3;
    bool valid = slot < npts;
    int pt = g_ord[valid ? slot : 0];

    int b = pt / ns;
    float p0 = qp[pt * 3 + 0];
    float p1 = qp[pt * 3 + 1];
    float p2 = qp[pt * 3 + 2];
    const float* tp = g_tp + (size_t)b * 3 * RR * RR * CC;

    // ---- primary triplane sample ----
    float4 feat = sample3(tp, p0, p1, p2, l);

    // ---- GEMV: [off(24)|w(8)] = feature @ [W_off|W_w] + bias (4 outputs/lane) ----
    float4 ow = *(const float4*)&sbc[4 * l];
#pragma unroll
    for (int c = 0; c < 32; c++) {
        float fc = __shfl_sync(FULL, COMP(feat, c & 3), c >> 2, 8);
        float4 wv = *(const float4*)&sWc[c * 32 + 4 * l];
        ow.x = fmaf(fc, wv.x, ow.x);
        ow.y = fmaf(fc, wv.y, ow.y);
        ow.z = fmaf(fc, wv.z, ow.z);
        ow.w = fmaf(fc, wv.w, ow.w);
    }

    // ---- S aux samples: A = sum_s w_s * aux_s, sw = sum_s w_s ----
    float4 A = make_float4(0.f, 0.f, 0.f, 0.f);
    float sw = 0.f;
#pragma unroll
    for (int s = 0; s < SPTS; s++) {
        float ox = __shfl_sync(FULL, COMP(ow, (3 * s    ) & 3), (3 * s    ) >> 2, 8);
        float oy = __shfl_sync(FULL, COMP(ow, (3 * s + 1) & 3), (3 * s + 1) >> 2, 8);
        float oz = __shfl_sync(FULL, COMP(ow, (3 * s + 2) & 3), (3 * s + 2) >> 2, 8);
        float ws = __shfl_sync(FULL, COMP(ow, (24 + s) & 3),    (24 + s) >> 2,    8);
        float4 aux = sample3(tp, p0 + ox, p1 + oy, p2 + oz, l);
        A.x = fmaf(ws, aux.x, A.x);
        A.y = fmaf(ws, aux.y, A.y);
        A.z = fmaf(ws, aux.z, A.z);
        A.w = fmaf(ws, aux.w, A.w);
        sw += ws;
    }

    // ---- final: out = A @ (W_v@W_out) + sw*(b_v@W_out) + b_out + feature ----
    float4 o;
    o.x = fmaf(sw, sbvo[4 * l    ], sbout[4 * l    ]) + feat.x;
    o.y = fmaf(sw, sbvo[4 * l + 1], sbout[4 * l + 1]) + feat.y;
    o.z = fmaf(sw, sbvo[4 * l + 2], sbout[4 * l + 2]) + feat.z;
    o.w = fmaf(sw, sbvo[4 * l + 3], sbout[4 * l + 3]) + feat.w;
#pragma unroll
    for (int c = 0; c < 32; c++) {
        float ac = __shfl_sync(FULL, COMP(A, c & 3), c >> 2, 8);
        float4 wv = *(const float4*)&sWvo[c * 32 + 4 * l];
        o.x = fmaf(ac, wv.x, o.x);
        o.y = fmaf(ac, wv.y, o.y);
        o.z = fmaf(ac, wv.z, o.z);
        o.w = fmaf(ac, wv.w, o.w);
    }

    if (valid) ((float4*)out)[(size_t)pt * 8 + l] = o;
}

// ---------------------------------------------------------------------------
// kernel_launch — inputs: 0 query_pos 1 c_xz 2 c_xy 3 c_yz 4 W_off 5 b_off
//                         6 W_w 7 b_w 8 W_v 9 b_v 10 W_out 11 b_out
// ---------------------------------------------------------------------------
extern "C" void kernel_launch(void* const* d_in, const int* in_sizes, int n_in,
                              void* d_out, int out_size) {
    const float* qp    = (const float*)d_in[0];
    const float* c_xz  = (const float*)d_in[1];
    const float* c_xy  = (const float*)d_in[2];
    const float* c_yz  = (const float*)d_in[3];
    const float* W_off = (const float*)d_in[4];
    const float* b_off = (const float*)d_in[5];
    const float* W_w   = (const float*)d_in[6];
    const float* b_w   = (const float*)d_in[7];
    const float* W_v   = (const float*)d_in[8];
    const float* b_v   = (const float*)d_in[9];
    const float* W_out = (const float*)d_in[10];
    const float* b_out = (const float*)d_in[11];

    int bs   = in_sizes[1] / (CC * RR * RR);   // = 2
    int ns   = in_sizes[0] / (bs * 3);         // = 50000
    int npts = bs * ns;

    // plane transpose + weight folding (independent of sort)
    transpose_planes<<<bs * 3 * RR, 256>>>(c_xz, c_xy, c_yz);
    prep_weights<<<1, 1024>>>(W_off, b_off, W_w, b_w, W_v, b_v, W_out);

    // spatial counting sort
    zero_bins<<<(NBINS + 255) / 256, 256>>>();
    hist_keys<<<(npts + 255) / 256, 256>>>(qp, ns, npts);
    scan_bins<<<1, 1024>>>();
    scatter_order<<<(npts + 255) / 256, 256>>>(npts);

    // main fused kernel: 64 points per 512-thread block
    int nblocks = (npts + 63) / 64;
    dat_kernel<<<nblocks, 512>>>(qp, b_out, (float*)d_out, ns, npts);
}